// round 10
// baseline (speedup 1.0000x reference)
#include <cuda_runtime.h>
#include <cuda_bf16.h>
#include <cstdint>

// ---------------------------------------------------------------------------
// WMSA round 10 (= round 9 resubmit after infra failure): everything on
// mma.sync bf16 (x3 split emulation of fp32).
//   convx   : roll+gather x -> bf16 hi/lo planes (window order)
//   qkv_mma : GEMM -> qkv bf16 hi/lo planes (split in epilogue)
//   attn    : tensor-core attention (QK^T, softmax on fragments, PV)
//   proj_mma: GEMM -> out fp32 (scatter + roll)
// ---------------------------------------------------------------------------

#define NWINS 1024
#define TPW   64

__device__ __align__(16) __nv_bfloat16 g_qkv_hi[(size_t)NWINS * TPW * 576];
__device__ __align__(16) __nv_bfloat16 g_qkv_lo[(size_t)NWINS * TPW * 576];
__device__ __align__(16) __nv_bfloat16 g_xs_hi[(size_t)NWINS * TPW * 192];
__device__ __align__(16) __nv_bfloat16 g_xs_lo[(size_t)NWINS * TPW * 192];
__device__ __align__(16) __nv_bfloat16 g_at_hi[(size_t)NWINS * TPW * 192];
__device__ __align__(16) __nv_bfloat16 g_at_lo[(size_t)NWINS * TPW * 192];

// split weights, transposed to [n][k]
__device__ __align__(16) __nv_bfloat16 WqkvT_hi[576 * 192];
__device__ __align__(16) __nv_bfloat16 WqkvT_lo[576 * 192];
__device__ __align__(16) __nv_bfloat16 WoutT_hi[192 * 192];
__device__ __align__(16) __nv_bfloat16 WoutT_lo[192 * 192];

// ------------------------------ helpers ------------------------------------
__device__ __forceinline__ uint32_t smem_u32(const void* p) {
    uint32_t a;
    asm("{ .reg .u64 t; cvta.to.shared.u64 t, %1; cvt.u32.u64 %0, t; }" : "=r"(a) : "l"(p));
    return a;
}
__device__ __forceinline__ uint32_t pack2(float a, float b) {   // mem order: a(lo half), b(hi half)
    uint32_t r;
    asm("cvt.rn.bf16x2.f32 %0, %1, %2;" : "=r"(r) : "f"(b), "f"(a));
    return r;
}
__device__ __forceinline__ void split2(float a, float b, uint32_t& h, uint32_t& l) {
    h = pack2(a, b);
    float ha = __uint_as_float(h << 16);
    float hb = __uint_as_float(h & 0xffff0000u);
    l = pack2(a - ha, b - hb);
}
__device__ __forceinline__ void ldsm_x4(uint32_t* r, uint32_t addr) {
    asm volatile("ldmatrix.sync.aligned.m8n8.x4.shared.b16 {%0,%1,%2,%3}, [%4];"
        : "=r"(r[0]), "=r"(r[1]), "=r"(r[2]), "=r"(r[3]) : "r"(addr));
}
__device__ __forceinline__ void mma_bf16(float* c, const uint32_t* a, const uint32_t* b) {
    asm volatile("mma.sync.aligned.m16n8k16.row.col.f32.bf16.bf16.f32 "
        "{%0,%1,%2,%3}, {%4,%5,%6,%7}, {%8,%9}, {%0,%1,%2,%3};"
        : "+f"(c[0]), "+f"(c[1]), "+f"(c[2]), "+f"(c[3])
        : "r"(a[0]), "r"(a[1]), "r"(a[2]), "r"(a[3]), "r"(b[0]), "r"(b[1]));
}

// ------------------------------ prep: weights ------------------------------
__global__ void prep_kernel(const float* __restrict__ Wqkv,
                            const float* __restrict__ Wout)
{
    int i = blockIdx.x * 256 + threadIdx.x;
    if (i < 576 * 192) {
        int n = i / 192, k = i % 192;
        float v = Wqkv[(size_t)k * 576 + n];
        __nv_bfloat16 h = __float2bfloat16(v);
        WqkvT_hi[i] = h;
        WqkvT_lo[i] = __float2bfloat16(v - __bfloat162float(h));
    }
    int j = i - 576 * 192;
    if (j >= 0 && j < 192 * 192) {
        int n = j / 192, k = j % 192;
        float v = Wout[(size_t)k * 192 + n];
        __nv_bfloat16 h = __float2bfloat16(v);
        WoutT_hi[j] = h;
        WoutT_lo[j] = __float2bfloat16(v - __bfloat162float(h));
    }
}

// ------------------------------ convert x ----------------------------------
__global__ __launch_bounds__(256) void convx_kernel(const float* __restrict__ x)
{
    const int t = threadIdx.x;
    const int row = blockIdx.x * 16 + (t >> 4);
    const int l16 = t & 15;
    const int tok = row & 63, bw = row >> 6;
    const int b = bw >> 9, w = bw & 511;
    const int z  = (((w >> 6) << 2)       + (tok >> 4)       + 2) & 31;
    const int y  = ((((w >> 3) & 7) << 2) + ((tok >> 2) & 3) + 2) & 31;
    const int xx = (((w & 7) << 2)        + (tok & 3)        + 2) & 31;
    const float* src = x + ((((size_t)b * 32 + z) * 32 + y) * 32 + xx) * 192 + l16 * 12;
    const size_t dst = (size_t)row * 192 + l16 * 12;
    #pragma unroll
    for (int i = 0; i < 3; ++i) {
        float4 v = *(const float4*)(src + i * 4);
        uint32_t h0, l0, h1, l1;
        split2(v.x, v.y, h0, l0);
        split2(v.z, v.w, h1, l1);
        *(uint2*)&g_xs_hi[dst + i * 4] = make_uint2(h0, h1);
        *(uint2*)&g_xs_lo[dst + i * 4] = make_uint2(l0, l1);
    }
}

// ------------------------------ GEMM core ----------------------------------
struct GemmSmem {
    __nv_bfloat16 AH[128 * 40];
    __nv_bfloat16 AL[128 * 40];
    __nv_bfloat16 BH[64 * 40];
    __nv_bfloat16 BL[64 * 40];
};

template <int KTOT>
__device__ __forceinline__ void gemm_mainloop(
    const __nv_bfloat16* __restrict__ gAh, const __nv_bfloat16* __restrict__ gAl,
    const __nv_bfloat16* __restrict__ gBh, const __nv_bfloat16* __restrict__ gBl,
    GemmSmem* sm, float acc[2][4][4])
{
    const int tid = threadIdx.x, lane = tid & 31, wid = tid >> 5;
    const int m0 = (wid & 3) * 32, n0 = (wid >> 2) * 32;
    const int half = tid & 1;
    const int arow = tid >> 1;
    const int brow = (tid >> 1) & 63;

    const uint4* gA_h = (const uint4*)(gAh + (size_t)arow * KTOT + half * 16);
    const uint4* gA_l = (const uint4*)(gAl + (size_t)arow * KTOT + half * 16);
    const uint4* gB_h = (const uint4*)(gBh + (size_t)brow * 192 + half * 16);
    const uint4* gB_l = (const uint4*)(gBl + (size_t)brow * 192 + half * 16);

    const uint32_t sAH = smem_u32(sm->AH), sAL = smem_u32(sm->AL);
    const uint32_t sBH = smem_u32(sm->BH), sBL = smem_u32(sm->BL);

    uint4 aPh[2], aPl[2], bPh[2], bPl[2];
    aPh[0] = gA_h[0]; aPh[1] = gA_h[1];
    aPl[0] = gA_l[0]; aPl[1] = gA_l[1];
    if (tid < 128) {
        bPh[0] = gB_h[0]; bPh[1] = gB_h[1];
        bPl[0] = gB_l[0]; bPl[1] = gB_l[1];
    }

    for (int kc = 0; kc < 6; ++kc) {
        __syncthreads();
        {
            *(uint4*)&sm->AH[arow * 40 + half * 16]     = aPh[0];
            *(uint4*)&sm->AH[arow * 40 + half * 16 + 8] = aPh[1];
            *(uint4*)&sm->AL[arow * 40 + half * 16]     = aPl[0];
            *(uint4*)&sm->AL[arow * 40 + half * 16 + 8] = aPl[1];
            if (tid < 128) {
                *(uint4*)&sm->BH[brow * 40 + half * 16]     = bPh[0];
                *(uint4*)&sm->BH[brow * 40 + half * 16 + 8] = bPh[1];
                *(uint4*)&sm->BL[brow * 40 + half * 16]     = bPl[0];
                *(uint4*)&sm->BL[brow * 40 + half * 16 + 8] = bPl[1];
            }
        }
        __syncthreads();
        if (kc < 5) {
            int o = (kc + 1) * 4;
            aPh[0] = gA_h[o]; aPh[1] = gA_h[o + 1];
            aPl[0] = gA_l[o]; aPl[1] = gA_l[o + 1];
            if (tid < 128) {
                bPh[0] = gB_h[o]; bPh[1] = gB_h[o + 1];
                bPl[0] = gB_l[o]; bPl[1] = gB_l[o + 1];
            }
        }
        #pragma unroll
        for (int ks = 0; ks < 2; ++ks) {
            uint32_t aH[2][4], aL[2][4], bH[8], bL[8];
            #pragma unroll
            for (int mf = 0; mf < 2; ++mf) {
                uint32_t off = (uint32_t)((m0 + mf * 16 + (lane & 15)) * 80
                                          + (ks * 2 + (lane >> 4)) * 16);
                ldsm_x4(aH[mf], sAH + off);
                ldsm_x4(aL[mf], sAL + off);
            }
            #pragma unroll
            for (int nf = 0; nf < 2; ++nf) {
                uint32_t off = (uint32_t)((n0 + nf * 16 + ((lane >> 4) & 1) * 8 + (lane & 7)) * 80
                                          + (ks * 2 + ((lane >> 3) & 1)) * 16);
                ldsm_x4(&bH[nf * 4], sBH + off);
                ldsm_x4(&bL[nf * 4], sBL + off);
            }
            #pragma unroll
            for (int mf = 0; mf < 2; ++mf)
                #pragma unroll
                for (int j = 0; j < 4; ++j) {
                    mma_bf16(acc[mf][j], aH[mf], &bH[j * 2]);
                    mma_bf16(acc[mf][j], aH[mf], &bL[j * 2]);
                    mma_bf16(acc[mf][j], aL[mf], &bH[j * 2]);
                }
        }
    }
}

// ------------------------------ K1: QKV ------------------------------------
// grid (512, 9), block 256. Epilogue splits fp32 result into bf16 hi/lo planes.
__global__ __launch_bounds__(256) void qkv_mma(const float* __restrict__ bqkv)
{
    __shared__ GemmSmem sm;
    const int tid = threadIdx.x, lane = tid & 31, wid = tid >> 5;
    const int mt = blockIdx.x, nt = blockIdx.y;
    const int m0 = (wid & 3) * 32, n0 = (wid >> 2) * 32;

    float acc[2][4][4] = {};
    gemm_mainloop<192>(
        g_xs_hi + (size_t)mt * 128 * 192, g_xs_lo + (size_t)mt * 128 * 192,
        WqkvT_hi + (size_t)nt * 64 * 192, WqkvT_lo + (size_t)nt * 64 * 192,
        &sm, acc);

    const int rbase = mt * 128 + m0 + (lane >> 2);
    #pragma unroll
    for (int j = 0; j < 4; ++j) {
        int col = nt * 64 + n0 + j * 8 + (lane & 3) * 2;
        float b0 = __ldg(&bqkv[col]), b1 = __ldg(&bqkv[col + 1]);
        #pragma unroll
        for (int mf = 0; mf < 2; ++mf) {
            uint32_t h0, l0, h1, l1;
            split2(acc[mf][j][0] + b0, acc[mf][j][1] + b1, h0, l0);
            split2(acc[mf][j][2] + b0, acc[mf][j][3] + b1, h1, l1);
            size_t i0 = (size_t)(rbase + mf * 16) * 576 + col;
            size_t i1 = (size_t)(rbase + mf * 16 + 8) * 576 + col;
            *(uint32_t*)&g_qkv_hi[i0] = h0;
            *(uint32_t*)&g_qkv_lo[i0] = l0;
            *(uint32_t*)&g_qkv_hi[i1] = h1;
            *(uint32_t*)&g_qkv_lo[i1] = l1;
        }
    }
}

// ------------------------------ K2: attention (tensor) ---------------------
// grid (1024, 6), block 64 (2 warps, 32 query rows each).
__global__ __launch_bounds__(64) void attn_kernel(const float* __restrict__ relp)
{
    __shared__ __nv_bfloat16 qHs[64 * 40], qLs[64 * 40];
    __shared__ __nv_bfloat16 kHs[64 * 40], kLs[64 * 40];
    __shared__ __nv_bfloat16 vHs[32 * 72], vLs[32 * 72];
    __shared__ float relS[343];

    const int bw = blockIdx.x, h = blockIdx.y;
    const int w = bw & 511;
    const int wz = w >> 6, wy = (w >> 3) & 7, wx = w & 7;
    const int tid = threadIdx.x, lane = tid & 31, wrp = tid >> 5;
    const int mb = wrp * 32;
    const float scale = 0.17677669529663687f;

    for (int i = tid; i < 343; i += 64) relS[i] = relp[h * 343 + i];

    {   // stage q,k [tok][40]; v transposed [c][72]
        size_t base = ((size_t)bw * 64 + tid) * 576 + h * 32;
        #pragma unroll
        for (int u = 0; u < 4; ++u) {
            *(uint4*)&qHs[tid * 40 + u * 8] = *(const uint4*)&g_qkv_hi[base + u * 8];
            *(uint4*)&qLs[tid * 40 + u * 8] = *(const uint4*)&g_qkv_lo[base + u * 8];
            *(uint4*)&kHs[tid * 40 + u * 8] = *(const uint4*)&g_qkv_hi[base + 192 + u * 8];
            *(uint4*)&kLs[tid * 40 + u * 8] = *(const uint4*)&g_qkv_lo[base + 192 + u * 8];
        }
        uint4 vh[4], vl[4];
        #pragma unroll
        for (int u = 0; u < 4; ++u) {
            vh[u] = *(const uint4*)&g_qkv_hi[base + 384 + u * 8];
            vl[u] = *(const uint4*)&g_qkv_lo[base + 384 + u * 8];
        }
        const __nv_bfloat16* ph = (const __nv_bfloat16*)vh;
        const __nv_bfloat16* pl = (const __nv_bfloat16*)vl;
        #pragma unroll
        for (int c = 0; c < 32; ++c) {
            vHs[c * 72 + tid] = ph[c];
            vLs[c * 72 + tid] = pl[c];
        }
    }
    __syncthreads();

    const uint32_t sQH = smem_u32(qHs), sQL = smem_u32(qLs);
    const uint32_t sKH = smem_u32(kHs), sKL = smem_u32(kLs);
    const uint32_t sVH = smem_u32(vHs), sVL = smem_u32(vLs);

    // ---- sim = q @ k^T (x3 split), 32x64 per warp ----
    float s[2][8][4];
    #pragma unroll
    for (int a = 0; a < 2; ++a)
        #pragma unroll
        for (int b2 = 0; b2 < 8; ++b2)
            #pragma unroll
            for (int c = 0; c < 4; ++c) s[a][b2][c] = 0.0f;

    #pragma unroll
    for (int ks = 0; ks < 2; ++ks) {
        uint32_t aH[2][4], aL[2][4], bH[4][4], bL[4][4];
        #pragma unroll
        for (int mt = 0; mt < 2; ++mt) {
            uint32_t off = (uint32_t)((mb + mt * 16 + (lane & 15)) * 80
                                      + (ks * 2 + (lane >> 4)) * 16);
            ldsm_x4(aH[mt], sQH + off);
            ldsm_x4(aL[mt], sQL + off);
        }
        #pragma unroll
        for (int grp = 0; grp < 4; ++grp) {
            uint32_t off = (uint32_t)((grp * 16 + ((lane >> 4) & 1) * 8 + (lane & 7)) * 80
                                      + (ks * 2 + ((lane >> 3) & 1)) * 16);
            ldsm_x4(bH[grp], sKH + off);
            ldsm_x4(bL[grp], sKL + off);
        }
        #pragma unroll
        for (int mt = 0; mt < 2; ++mt)
            #pragma unroll
            for (int grp = 0; grp < 4; ++grp)
                #pragma unroll
                for (int j = 0; j < 2; ++j) {
                    mma_bf16(s[mt][grp * 2 + j], aH[mt], &bH[grp][j * 2]);
                    mma_bf16(s[mt][grp * 2 + j], aH[mt], &bL[grp][j * 2]);
                    mma_bf16(s[mt][grp * 2 + j], aL[mt], &bH[grp][j * 2]);
                }
    }

    // ---- scale + bias + mask on fragments ----
    const int g = lane >> 2, tg2 = (lane & 3) * 2;
    int linP[4]; bool pz2[4], py2[4], px2[4];
    #pragma unroll
    for (int mt = 0; mt < 2; ++mt)
        #pragma unroll
        for (int r = 0; r < 2; ++r) {
            int p = mb + mt * 16 + g + r * 8;
            int pz = p >> 4, py = (p >> 2) & 3, px = p & 3;
            linP[mt * 2 + r] = pz * 49 + py * 7 + px;
            pz2[mt * 2 + r] = pz < 2; py2[mt * 2 + r] = py < 2; px2[mt * 2 + r] = px < 2;
        }
    int linQ[16]; bool qz2[16], qy2[16], qx2[16];
    #pragma unroll
    for (int nt = 0; nt < 8; ++nt)
        #pragma unroll
        for (int t = 0; t < 2; ++t) {
            int qq = nt * 8 + tg2 + t;
            int qz = qq >> 4, qy = (qq >> 2) & 3, qx = qq & 3;
            linQ[nt * 2 + t] = qz * 49 + qy * 7 + qx;
            qz2[nt * 2 + t] = qz < 2; qy2[nt * 2 + t] = qy < 2; qx2[nt * 2 + t] = qx < 2;
        }
    const bool mz = (wz == 7), my = (wy == 7), mx = (wx == 7);
    #pragma unroll
    for (int mt = 0; mt < 2; ++mt)
        #pragma unroll
        for (int nt = 0; nt < 8; ++nt)
            #pragma unroll
            for (int r = 0; r < 2; ++r)
                #pragma unroll
                for (int t = 0; t < 2; ++t) {
                    int pi = mt * 2 + r, qi = nt * 2 + t;
                    float v = s[mt][nt][r * 2 + t] * scale
                            + relS[linP[pi] - linQ[qi] + 171];
                    if ((mz && (pz2[pi] != qz2[qi])) ||
                        (my && (py2[pi] != qy2[qi])) ||
                        (mx && (px2[pi] != qx2[qi]))) v = -1e30f;
                    s[mt][nt][r * 2 + t] = v;
                }

    // ---- softmax on fragments (rows reduce across 4 lanes) ----
    float inv[4];
    #pragma unroll
    for (int mt = 0; mt < 2; ++mt)
        #pragma unroll
        for (int r = 0; r < 2; ++r) {
            float mxv = -1e30f;
            #pragma unroll
            for (int nt = 0; nt < 8; ++nt)
                #pragma unroll
                for (int t = 0; t < 2; ++t)
                    mxv = fmaxf(mxv, s[mt][nt][r * 2 + t]);
            mxv = fmaxf(mxv, __shfl_xor_sync(0xffffffffu, mxv, 1));
            mxv = fmaxf(mxv, __shfl_xor_sync(0xffffffffu, mxv, 2));
            float sum = 0.0f;
            #pragma unroll
            for (int nt = 0; nt < 8; ++nt)
                #pragma unroll
                for (int t = 0; t < 2; ++t) {
                    float e = __expf(s[mt][nt][r * 2 + t] - mxv);
                    s[mt][nt][r * 2 + t] = e;
                    sum += e;
                }
            sum += __shfl_xor_sync(0xffffffffu, sum, 1);
            sum += __shfl_xor_sync(0xffffffffu, sum, 2);
            inv[mt * 2 + r] = 1.0f / sum;
        }

    // ---- out = probs @ v (x3 split), 32x32 per warp; normalize at end ----
    float o[2][4][4];
    #pragma unroll
    for (int a = 0; a < 2; ++a)
        #pragma unroll
        for (int b2 = 0; b2 < 4; ++b2)
            #pragma unroll
            for (int c = 0; c < 4; ++c) o[a][b2][c] = 0.0f;

    #pragma unroll
    for (int ks = 0; ks < 4; ++ks) {
        uint32_t bH[2][4], bL[2][4];
        #pragma unroll
        for (int grp = 0; grp < 2; ++grp) {
            uint32_t off = (uint32_t)((grp * 16 + ((lane >> 4) & 1) * 8 + (lane & 7)) * 144
                                      + (ks * 2 + ((lane >> 3) & 1)) * 16);
            ldsm_x4(bH[grp], sVH + off);
            ldsm_x4(bL[grp], sVL + off);
        }
        #pragma unroll
        for (int mt = 0; mt < 2; ++mt) {
            uint32_t aPH[4], aPL[4];
            split2(s[mt][2 * ks][0],     s[mt][2 * ks][1],     aPH[0], aPL[0]);
            split2(s[mt][2 * ks][2],     s[mt][2 * ks][3],     aPH[1], aPL[1]);
            split2(s[mt][2 * ks + 1][0], s[mt][2 * ks + 1][1], aPH[2], aPL[2]);
            split2(s[mt][2 * ks + 1][2], s[mt][2 * ks + 1][3], aPH[3], aPL[3]);
            #pragma unroll
            for (int grp = 0; grp < 2; ++grp)
                #pragma unroll
                for (int j = 0; j < 2; ++j) {
                    mma_bf16(o[mt][grp * 2 + j], aPH, &bH[grp][j * 2]);
                    mma_bf16(o[mt][grp * 2 + j], aPH, &bL[grp][j * 2]);
                    mma_bf16(o[mt][grp * 2 + j], aPL, &bH[grp][j * 2]);
                }
        }
    }

    // ---- epilogue: normalize, split, store to g_at hi/lo planes ----
    #pragma unroll
    for (int mt = 0; mt < 2; ++mt) {
        int r0 = mb + mt * 16 + g;
        #pragma unroll
        for (int nt = 0; nt < 4; ++nt) {
            int col = h * 32 + nt * 8 + tg2;
            uint32_t h0, l0, h1, l1;
            split2(o[mt][nt][0] * inv[mt * 2],     o[mt][nt][1] * inv[mt * 2],     h0, l0);
            split2(o[mt][nt][2] * inv[mt * 2 + 1], o[mt][nt][3] * inv[mt * 2 + 1], h1, l1);
            size_t i0 = ((size_t)bw * 64 + r0) * 192 + col;
            size_t i1 = ((size_t)bw * 64 + r0 + 8) * 192 + col;
            *(uint32_t*)&g_at_hi[i0] = h0;
            *(uint32_t*)&g_at_lo[i0] = l0;
            *(uint32_t*)&g_at_hi[i1] = h1;
            *(uint32_t*)&g_at_lo[i1] = l1;
        }
    }
}

// ------------------------------ K3: out proj -------------------------------
// grid (512, 3), block 256. Scatter epilogue (inverse window + roll +2).
__global__ __launch_bounds__(256) void proj_mma(
    const float* __restrict__ bout, float* __restrict__ out)
{
    __shared__ GemmSmem sm;
    const int tid = threadIdx.x, lane = tid & 31, wid = tid >> 5;
    const int mt = blockIdx.x, nt = blockIdx.y;
    const int m0 = (wid & 3) * 32, n0 = (wid >> 2) * 32;

    float acc[2][4][4] = {};
    gemm_mainloop<192>(
        g_at_hi + (size_t)mt * 128 * 192, g_at_lo + (size_t)mt * 128 * 192,
        WoutT_hi + (size_t)nt * 64 * 192, WoutT_lo + (size_t)nt * 64 * 192,
        &sm, acc);

    size_t obase[2][2];
    #pragma unroll
    for (int mf = 0; mf < 2; ++mf)
        #pragma unroll
        for (int rr = 0; rr < 2; ++rr) {
            int rg = mt * 128 + m0 + mf * 16 + rr * 8 + (lane >> 2);
            int tok = rg & 63, bw = rg >> 6;
            int b = bw >> 9, w = bw & 511;
            int z  = (((w >> 6) << 2)       + (tok >> 4)       + 2) & 31;
            int y  = ((((w >> 3) & 7) << 2) + ((tok >> 2) & 3) + 2) & 31;
            int xx = (((w & 7) << 2)        + (tok & 3)        + 2) & 31;
            obase[mf][rr] = ((((size_t)b * 32 + z) * 32 + y) * 32 + xx) * 192;
        }

    #pragma unroll
    for (int j = 0; j < 4; ++j) {
        int col = nt * 64 + n0 + j * 8 + (lane & 3) * 2;
        float b0 = __ldg(&bout[col]), b1 = __ldg(&bout[col + 1]);
        #pragma unroll
        for (int mf = 0; mf < 2; ++mf) {
            *(float2*)&out[obase[mf][0] + col] =
                make_float2(acc[mf][j][0] + b0, acc[mf][j][1] + b1);
            *(float2*)&out[obase[mf][1] + col] =
                make_float2(acc[mf][j][2] + b0, acc[mf][j][3] + b1);
        }
    }
}

// ------------------------------- launch ------------------------------------
extern "C" void kernel_launch(void* const* d_in, const int* in_sizes, int n_in,
                              void* d_out, int out_size)
{
    const float* x    = (const float*)d_in[0];
    const float* Wqkv = (const float*)d_in[1];
    const float* bqkv = (const float*)d_in[2];
    const float* relp = (const float*)d_in[3];
    const float* Wout = (const float*)d_in[4];
    const float* bout = (const float*)d_in[5];
    float* out = (float*)d_out;

    prep_kernel<<<576, 256>>>(Wqkv, Wout);
    convx_kernel<<<4096, 256>>>(x);
    qkv_mma<<<dim3(512, 9), 256>>>(bqkv);
    attn_kernel<<<dim3(1024, 6), 64>>>(relp);
    proj_mma<<<dim3(512, 3), 256>>>(bout, out);
}

// round 11
// speedup vs baseline: 1.1609x; 1.1609x over previous
#include <cuda_runtime.h>
#include <cuda_bf16.h>
#include <cstdint>

// ---------------------------------------------------------------------------
// WMSA round 11: attn re-parallelized (4 warps x 16 rows, ILP-reordered mmas).
// GEMMs unchanged from round 10 (mma.sync bf16 x3 split).
// ---------------------------------------------------------------------------

#define NWINS 1024
#define TPW   64

__device__ __align__(16) __nv_bfloat16 g_qkv_hi[(size_t)NWINS * TPW * 576];
__device__ __align__(16) __nv_bfloat16 g_qkv_lo[(size_t)NWINS * TPW * 576];
__device__ __align__(16) __nv_bfloat16 g_xs_hi[(size_t)NWINS * TPW * 192];
__device__ __align__(16) __nv_bfloat16 g_xs_lo[(size_t)NWINS * TPW * 192];
__device__ __align__(16) __nv_bfloat16 g_at_hi[(size_t)NWINS * TPW * 192];
__device__ __align__(16) __nv_bfloat16 g_at_lo[(size_t)NWINS * TPW * 192];

__device__ __align__(16) __nv_bfloat16 WqkvT_hi[576 * 192];
__device__ __align__(16) __nv_bfloat16 WqkvT_lo[576 * 192];
__device__ __align__(16) __nv_bfloat16 WoutT_hi[192 * 192];
__device__ __align__(16) __nv_bfloat16 WoutT_lo[192 * 192];

// ------------------------------ helpers ------------------------------------
__device__ __forceinline__ uint32_t smem_u32(const void* p) {
    uint32_t a;
    asm("{ .reg .u64 t; cvta.to.shared.u64 t, %1; cvt.u32.u64 %0, t; }" : "=r"(a) : "l"(p));
    return a;
}
__device__ __forceinline__ uint32_t pack2(float a, float b) {
    uint32_t r;
    asm("cvt.rn.bf16x2.f32 %0, %1, %2;" : "=r"(r) : "f"(b), "f"(a));
    return r;
}
__device__ __forceinline__ void split2(float a, float b, uint32_t& h, uint32_t& l) {
    h = pack2(a, b);
    float ha = __uint_as_float(h << 16);
    float hb = __uint_as_float(h & 0xffff0000u);
    l = pack2(a - ha, b - hb);
}
__device__ __forceinline__ void ldsm_x4(uint32_t* r, uint32_t addr) {
    asm volatile("ldmatrix.sync.aligned.m8n8.x4.shared.b16 {%0,%1,%2,%3}, [%4];"
        : "=r"(r[0]), "=r"(r[1]), "=r"(r[2]), "=r"(r[3]) : "r"(addr));
}
__device__ __forceinline__ void mma_bf16(float* c, const uint32_t* a, const uint32_t* b) {
    asm volatile("mma.sync.aligned.m16n8k16.row.col.f32.bf16.bf16.f32 "
        "{%0,%1,%2,%3}, {%4,%5,%6,%7}, {%8,%9}, {%0,%1,%2,%3};"
        : "+f"(c[0]), "+f"(c[1]), "+f"(c[2]), "+f"(c[3])
        : "r"(a[0]), "r"(a[1]), "r"(a[2]), "r"(a[3]), "r"(b[0]), "r"(b[1]));
}

// ------------------------------ prep: weights ------------------------------
__global__ void prep_kernel(const float* __restrict__ Wqkv,
                            const float* __restrict__ Wout)
{
    int i = blockIdx.x * 256 + threadIdx.x;
    if (i < 576 * 192) {
        int n = i / 192, k = i % 192;
        float v = Wqkv[(size_t)k * 576 + n];
        __nv_bfloat16 h = __float2bfloat16(v);
        WqkvT_hi[i] = h;
        WqkvT_lo[i] = __float2bfloat16(v - __bfloat162float(h));
    }
    int j = i - 576 * 192;
    if (j >= 0 && j < 192 * 192) {
        int n = j / 192, k = j % 192;
        float v = Wout[(size_t)k * 192 + n];
        __nv_bfloat16 h = __float2bfloat16(v);
        WoutT_hi[j] = h;
        WoutT_lo[j] = __float2bfloat16(v - __bfloat162float(h));
    }
}

// ------------------------------ convert x ----------------------------------
__global__ __launch_bounds__(256) void convx_kernel(const float* __restrict__ x)
{
    const int t = threadIdx.x;
    const int row = blockIdx.x * 16 + (t >> 4);
    const int l16 = t & 15;
    const int tok = row & 63, bw = row >> 6;
    const int b = bw >> 9, w = bw & 511;
    const int z  = (((w >> 6) << 2)       + (tok >> 4)       + 2) & 31;
    const int y  = ((((w >> 3) & 7) << 2) + ((tok >> 2) & 3) + 2) & 31;
    const int xx = (((w & 7) << 2)        + (tok & 3)        + 2) & 31;
    const float* src = x + ((((size_t)b * 32 + z) * 32 + y) * 32 + xx) * 192 + l16 * 12;
    const size_t dst = (size_t)row * 192 + l16 * 12;
    #pragma unroll
    for (int i = 0; i < 3; ++i) {
        float4 v = *(const float4*)(src + i * 4);
        uint32_t h0, l0, h1, l1;
        split2(v.x, v.y, h0, l0);
        split2(v.z, v.w, h1, l1);
        *(uint2*)&g_xs_hi[dst + i * 4] = make_uint2(h0, h1);
        *(uint2*)&g_xs_lo[dst + i * 4] = make_uint2(l0, l1);
    }
}

// ------------------------------ GEMM core ----------------------------------
struct GemmSmem {
    __nv_bfloat16 AH[128 * 40];
    __nv_bfloat16 AL[128 * 40];
    __nv_bfloat16 BH[64 * 40];
    __nv_bfloat16 BL[64 * 40];
};

template <int KTOT>
__device__ __forceinline__ void gemm_mainloop(
    const __nv_bfloat16* __restrict__ gAh, const __nv_bfloat16* __restrict__ gAl,
    const __nv_bfloat16* __restrict__ gBh, const __nv_bfloat16* __restrict__ gBl,
    GemmSmem* sm, float acc[2][4][4])
{
    const int tid = threadIdx.x, lane = tid & 31, wid = tid >> 5;
    const int m0 = (wid & 3) * 32, n0 = (wid >> 2) * 32;
    const int half = tid & 1;
    const int arow = tid >> 1;
    const int brow = (tid >> 1) & 63;

    const uint4* gA_h = (const uint4*)(gAh + (size_t)arow * KTOT + half * 16);
    const uint4* gA_l = (const uint4*)(gAl + (size_t)arow * KTOT + half * 16);
    const uint4* gB_h = (const uint4*)(gBh + (size_t)brow * 192 + half * 16);
    const uint4* gB_l = (const uint4*)(gBl + (size_t)brow * 192 + half * 16);

    const uint32_t sAH = smem_u32(sm->AH), sAL = smem_u32(sm->AL);
    const uint32_t sBH = smem_u32(sm->BH), sBL = smem_u32(sm->BL);

    uint4 aPh[2], aPl[2], bPh[2], bPl[2];
    aPh[0] = gA_h[0]; aPh[1] = gA_h[1];
    aPl[0] = gA_l[0]; aPl[1] = gA_l[1];
    if (tid < 128) {
        bPh[0] = gB_h[0]; bPh[1] = gB_h[1];
        bPl[0] = gB_l[0]; bPl[1] = gB_l[1];
    }

    for (int kc = 0; kc < 6; ++kc) {
        __syncthreads();
        {
            *(uint4*)&sm->AH[arow * 40 + half * 16]     = aPh[0];
            *(uint4*)&sm->AH[arow * 40 + half * 16 + 8] = aPh[1];
            *(uint4*)&sm->AL[arow * 40 + half * 16]     = aPl[0];
            *(uint4*)&sm->AL[arow * 40 + half * 16 + 8] = aPl[1];
            if (tid < 128) {
                *(uint4*)&sm->BH[brow * 40 + half * 16]     = bPh[0];
                *(uint4*)&sm->BH[brow * 40 + half * 16 + 8] = bPh[1];
                *(uint4*)&sm->BL[brow * 40 + half * 16]     = bPl[0];
                *(uint4*)&sm->BL[brow * 40 + half * 16 + 8] = bPl[1];
            }
        }
        __syncthreads();
        if (kc < 5) {
            int o = (kc + 1) * 4;
            aPh[0] = gA_h[o]; aPh[1] = gA_h[o + 1];
            aPl[0] = gA_l[o]; aPl[1] = gA_l[o + 1];
            if (tid < 128) {
                bPh[0] = gB_h[o]; bPh[1] = gB_h[o + 1];
                bPl[0] = gB_l[o]; bPl[1] = gB_l[o + 1];
            }
        }
        #pragma unroll
        for (int ks = 0; ks < 2; ++ks) {
            uint32_t aH[2][4], aL[2][4], bH[8], bL[8];
            #pragma unroll
            for (int mf = 0; mf < 2; ++mf) {
                uint32_t off = (uint32_t)((m0 + mf * 16 + (lane & 15)) * 80
                                          + (ks * 2 + (lane >> 4)) * 16);
                ldsm_x4(aH[mf], sAH + off);
                ldsm_x4(aL[mf], sAL + off);
            }
            #pragma unroll
            for (int nf = 0; nf < 2; ++nf) {
                uint32_t off = (uint32_t)((n0 + nf * 16 + ((lane >> 4) & 1) * 8 + (lane & 7)) * 80
                                          + (ks * 2 + ((lane >> 3) & 1)) * 16);
                ldsm_x4(&bH[nf * 4], sBH + off);
                ldsm_x4(&bL[nf * 4], sBL + off);
            }
            // ILP: pass-major order (independent accumulators back-to-back)
            #pragma unroll
            for (int mf = 0; mf < 2; ++mf)
                #pragma unroll
                for (int j = 0; j < 4; ++j)
                    mma_bf16(acc[mf][j], aH[mf], &bH[j * 2]);
            #pragma unroll
            for (int mf = 0; mf < 2; ++mf)
                #pragma unroll
                for (int j = 0; j < 4; ++j)
                    mma_bf16(acc[mf][j], aH[mf], &bL[j * 2]);
            #pragma unroll
            for (int mf = 0; mf < 2; ++mf)
                #pragma unroll
                for (int j = 0; j < 4; ++j)
                    mma_bf16(acc[mf][j], aL[mf], &bH[j * 2]);
        }
    }
}

// ------------------------------ K1: QKV ------------------------------------
__global__ __launch_bounds__(256) void qkv_mma(const float* __restrict__ bqkv)
{
    __shared__ GemmSmem sm;
    const int tid = threadIdx.x, lane = tid & 31, wid = tid >> 5;
    const int mt = blockIdx.x, nt = blockIdx.y;
    const int m0 = (wid & 3) * 32, n0 = (wid >> 2) * 32;

    float acc[2][4][4] = {};
    gemm_mainloop<192>(
        g_xs_hi + (size_t)mt * 128 * 192, g_xs_lo + (size_t)mt * 128 * 192,
        WqkvT_hi + (size_t)nt * 64 * 192, WqkvT_lo + (size_t)nt * 64 * 192,
        &sm, acc);

    const int rbase = mt * 128 + m0 + (lane >> 2);
    #pragma unroll
    for (int j = 0; j < 4; ++j) {
        int col = nt * 64 + n0 + j * 8 + (lane & 3) * 2;
        float b0 = __ldg(&bqkv[col]), b1 = __ldg(&bqkv[col + 1]);
        #pragma unroll
        for (int mf = 0; mf < 2; ++mf) {
            uint32_t h0, l0, h1, l1;
            split2(acc[mf][j][0] + b0, acc[mf][j][1] + b1, h0, l0);
            split2(acc[mf][j][2] + b0, acc[mf][j][3] + b1, h1, l1);
            size_t i0 = (size_t)(rbase + mf * 16) * 576 + col;
            size_t i1 = (size_t)(rbase + mf * 16 + 8) * 576 + col;
            *(uint32_t*)&g_qkv_hi[i0] = h0;
            *(uint32_t*)&g_qkv_lo[i0] = l0;
            *(uint32_t*)&g_qkv_hi[i1] = h1;
            *(uint32_t*)&g_qkv_lo[i1] = l1;
        }
    }
}

// ------------------------------ K2: attention (tensor) ---------------------
// grid (1024, 6), block 128 (4 warps, 16 query rows each).
__global__ __launch_bounds__(128) void attn_kernel(const float* __restrict__ relp)
{
    __shared__ __nv_bfloat16 qHs[64 * 40], qLs[64 * 40];
    __shared__ __nv_bfloat16 kHs[64 * 40], kLs[64 * 40];
    __shared__ __nv_bfloat16 vHs[32 * 72], vLs[32 * 72];
    __shared__ float relS[343];

    const int bw = blockIdx.x, h = blockIdx.y;
    const int w = bw & 511;
    const int wz = w >> 6, wy = (w >> 3) & 7, wx = w & 7;
    const int tid = threadIdx.x, lane = tid & 31, wrp = tid >> 5;
    const int mb = wrp * 16;
    const float scale = 0.17677669529663687f;

    for (int i = tid; i < 343; i += 128) relS[i] = relp[h * 343 + i];

    {   // stage q,k [tok][40] (threads split q/k); v transposed [c][72]
        const int srow = tid & 63, sel = tid >> 6;     // sel 0: q, 1: k
        size_t base = ((size_t)bw * 64 + srow) * 576 + h * 32 + (size_t)sel * 192;
        __nv_bfloat16* dH = sel ? kHs : qHs;
        __nv_bfloat16* dL = sel ? kLs : qLs;
        #pragma unroll
        for (int u = 0; u < 4; ++u) {
            *(uint4*)&dH[srow * 40 + u * 8] = *(const uint4*)&g_qkv_hi[base + u * 8];
            *(uint4*)&dL[srow * 40 + u * 8] = *(const uint4*)&g_qkv_lo[base + u * 8];
        }
        if (tid < 64) {
            size_t vb = ((size_t)bw * 64 + tid) * 576 + h * 32 + 384;
            uint4 vh[4], vl[4];
            #pragma unroll
            for (int u = 0; u < 4; ++u) {
                vh[u] = *(const uint4*)&g_qkv_hi[vb + u * 8];
                vl[u] = *(const uint4*)&g_qkv_lo[vb + u * 8];
            }
            const __nv_bfloat16* ph = (const __nv_bfloat16*)vh;
            const __nv_bfloat16* pl = (const __nv_bfloat16*)vl;
            #pragma unroll
            for (int c = 0; c < 32; ++c) {
                vHs[c * 72 + tid] = ph[c];
                vLs[c * 72 + tid] = pl[c];
            }
        }
    }
    __syncthreads();

    const uint32_t sQH = smem_u32(qHs), sQL = smem_u32(qLs);
    const uint32_t sKH = smem_u32(kHs), sKL = smem_u32(kLs);
    const uint32_t sVH = smem_u32(vHs), sVL = smem_u32(vLs);

    // ---- sim = q @ k^T (x3 split), 16x64 per warp ----
    float s[8][4];
    #pragma unroll
    for (int b2 = 0; b2 < 8; ++b2)
        #pragma unroll
        for (int c = 0; c < 4; ++c) s[b2][c] = 0.0f;

    #pragma unroll
    for (int ks = 0; ks < 2; ++ks) {
        uint32_t aH[4], aL[4], bH[4][4], bL[4][4];
        {
            uint32_t off = (uint32_t)((mb + (lane & 15)) * 80
                                      + (ks * 2 + (lane >> 4)) * 16);
            ldsm_x4(aH, sQH + off);
            ldsm_x4(aL, sQL + off);
        }
        #pragma unroll
        for (int grp = 0; grp < 4; ++grp) {
            uint32_t off = (uint32_t)((grp * 16 + ((lane >> 4) & 1) * 8 + (lane & 7)) * 80
                                      + (ks * 2 + ((lane >> 3) & 1)) * 16);
            ldsm_x4(bH[grp], sKH + off);
            ldsm_x4(bL[grp], sKL + off);
        }
        // pass-major (8 independent accumulator chains per pass)
        #pragma unroll
        for (int grp = 0; grp < 4; ++grp)
            #pragma unroll
            for (int j = 0; j < 2; ++j)
                mma_bf16(s[grp * 2 + j], aH, &bH[grp][j * 2]);
        #pragma unroll
        for (int grp = 0; grp < 4; ++grp)
            #pragma unroll
            for (int j = 0; j < 2; ++j)
                mma_bf16(s[grp * 2 + j], aH, &bL[grp][j * 2]);
        #pragma unroll
        for (int grp = 0; grp < 4; ++grp)
            #pragma unroll
            for (int j = 0; j < 2; ++j)
                mma_bf16(s[grp * 2 + j], aL, &bH[grp][j * 2]);
    }

    // ---- scale + bias + mask on fragments ----
    const int g = lane >> 2, tg2 = (lane & 3) * 2;
    int linP[2]; bool pz2[2], py2[2], px2[2];
    #pragma unroll
    for (int r = 0; r < 2; ++r) {
        int p = mb + g + r * 8;
        int pz = p >> 4, py = (p >> 2) & 3, px = p & 3;
        linP[r] = pz * 49 + py * 7 + px;
        pz2[r] = pz < 2; py2[r] = py < 2; px2[r] = px < 2;
    }
    int linQ[16]; bool qz2[16], qy2[16], qx2[16];
    #pragma unroll
    for (int nt = 0; nt < 8; ++nt)
        #pragma unroll
        for (int t = 0; t < 2; ++t) {
            int qq = nt * 8 + tg2 + t;
            int qz = qq >> 4, qy = (qq >> 2) & 3, qx = qq & 3;
            linQ[nt * 2 + t] = qz * 49 + qy * 7 + qx;
            qz2[nt * 2 + t] = qz < 2; qy2[nt * 2 + t] = qy < 2; qx2[nt * 2 + t] = qx < 2;
        }
    const bool mz = (wz == 7), my = (wy == 7), mx = (wx == 7);
    #pragma unroll
    for (int nt = 0; nt < 8; ++nt)
        #pragma unroll
        for (int r = 0; r < 2; ++r)
            #pragma unroll
            for (int t = 0; t < 2; ++t) {
                int qi = nt * 2 + t;
                float v = s[nt][r * 2 + t] * scale
                        + relS[linP[r] - linQ[qi] + 171];
                if ((mz && (pz2[r] != qz2[qi])) ||
                    (my && (py2[r] != qy2[qi])) ||
                    (mx && (px2[r] != qx2[qi]))) v = -1e30f;
                s[nt][r * 2 + t] = v;
            }

    // ---- softmax on fragments ----
    float inv[2];
    #pragma unroll
    for (int r = 0; r < 2; ++r) {
        float mxv = -1e30f;
        #pragma unroll
        for (int nt = 0; nt < 8; ++nt)
            #pragma unroll
            for (int t = 0; t < 2; ++t)
                mxv = fmaxf(mxv, s[nt][r * 2 + t]);
        mxv = fmaxf(mxv, __shfl_xor_sync(0xffffffffu, mxv, 1));
        mxv = fmaxf(mxv, __shfl_xor_sync(0xffffffffu, mxv, 2));
        float sum = 0.0f;
        #pragma unroll
        for (int nt = 0; nt < 8; ++nt)
            #pragma unroll
            for (int t = 0; t < 2; ++t) {
                float e = __expf(s[nt][r * 2 + t] - mxv);
                s[nt][r * 2 + t] = e;
                sum += e;
            }
        sum += __shfl_xor_sync(0xffffffffu, sum, 1);
        sum += __shfl_xor_sync(0xffffffffu, sum, 2);
        inv[r] = 1.0f / sum;
    }

    // ---- out = probs @ v (x3 split), 16x32 per warp ----
    float o[4][4];
    #pragma unroll
    for (int b2 = 0; b2 < 4; ++b2)
        #pragma unroll
        for (int c = 0; c < 4; ++c) o[b2][c] = 0.0f;

    #pragma unroll
    for (int ks = 0; ks < 4; ++ks) {
        uint32_t bH[2][4], bL[2][4];
        #pragma unroll
        for (int grp = 0; grp < 2; ++grp) {
            uint32_t off = (uint32_t)((grp * 16 + ((lane >> 4) & 1) * 8 + (lane & 7)) * 144
                                      + (ks * 2 + ((lane >> 3) & 1)) * 16);
            ldsm_x4(bH[grp], sVH + off);
            ldsm_x4(bL[grp], sVL + off);
        }
        uint32_t aPH[4], aPL[4];
        split2(s[2 * ks][0],     s[2 * ks][1],     aPH[0], aPL[0]);
        split2(s[2 * ks][2],     s[2 * ks][3],     aPH[1], aPL[1]);
        split2(s[2 * ks + 1][0], s[2 * ks + 1][1], aPH[2], aPL[2]);
        split2(s[2 * ks + 1][2], s[2 * ks + 1][3], aPH[3], aPL[3]);
        #pragma unroll
        for (int grp = 0; grp < 2; ++grp)
            #pragma unroll
            for (int j = 0; j < 2; ++j)
                mma_bf16(o[grp * 2 + j], aPH, &bH[grp][j * 2]);
        #pragma unroll
        for (int grp = 0; grp < 2; ++grp)
            #pragma unroll
            for (int j = 0; j < 2; ++j)
                mma_bf16(o[grp * 2 + j], aPH, &bL[grp][j * 2]);
        #pragma unroll
        for (int grp = 0; grp < 2; ++grp)
            #pragma unroll
            for (int j = 0; j < 2; ++j)
                mma_bf16(o[grp * 2 + j], aPL, &bH[grp][j * 2]);
    }

    // ---- epilogue: normalize, split, store ----
    {
        int r0 = mb + g;
        #pragma unroll
        for (int nt = 0; nt < 4; ++nt) {
            int col = h * 32 + nt * 8 + tg2;
            uint32_t h0, l0, h1, l1;
            split2(o[nt][0] * inv[0], o[nt][1] * inv[0], h0, l0);
            split2(o[nt][2] * inv[1], o[nt][3] * inv[1], h1, l1);
            size_t i0 = ((size_t)bw * 64 + r0) * 192 + col;
            size_t i1 = ((size_t)bw * 64 + r0 + 8) * 192 + col;
            *(uint32_t*)&g_at_hi[i0] = h0;
            *(uint32_t*)&g_at_lo[i0] = l0;
            *(uint32_t*)&g_at_hi[i1] = h1;
            *(uint32_t*)&g_at_lo[i1] = l1;
        }
    }
}

// ------------------------------ K3: out proj -------------------------------
__global__ __launch_bounds__(256) void proj_mma(
    const float* __restrict__ bout, float* __restrict__ out)
{
    __shared__ GemmSmem sm;
    const int tid = threadIdx.x, lane = tid & 31, wid = tid >> 5;
    const int mt = blockIdx.x, nt = blockIdx.y;
    const int m0 = (wid & 3) * 32, n0 = (wid >> 2) * 32;

    float acc[2][4][4] = {};
    gemm_mainloop<192>(
        g_at_hi + (size_t)mt * 128 * 192, g_at_lo + (size_t)mt * 128 * 192,
        WoutT_hi + (size_t)nt * 64 * 192, WoutT_lo + (size_t)nt * 64 * 192,
        &sm, acc);

    size_t obase[2][2];
    #pragma unroll
    for (int mf = 0; mf < 2; ++mf)
        #pragma unroll
        for (int rr = 0; rr < 2; ++rr) {
            int rg = mt * 128 + m0 + mf * 16 + rr * 8 + (lane >> 2);
            int tok = rg & 63, bw = rg >> 6;
            int b = bw >> 9, w = bw & 511;
            int z  = (((w >> 6) << 2)       + (tok >> 4)       + 2) & 31;
            int y  = ((((w >> 3) & 7) << 2) + ((tok >> 2) & 3) + 2) & 31;
            int xx = (((w & 7) << 2)        + (tok & 3)        + 2) & 31;
            obase[mf][rr] = ((((size_t)b * 32 + z) * 32 + y) * 32 + xx) * 192;
        }

    #pragma unroll
    for (int j = 0; j < 4; ++j) {
        int col = nt * 64 + n0 + j * 8 + (lane & 3) * 2;
        float b0 = __ldg(&bout[col]), b1 = __ldg(&bout[col + 1]);
        #pragma unroll
        for (int mf = 0; mf < 2; ++mf) {
            *(float2*)&out[obase[mf][0] + col] =
                make_float2(acc[mf][j][0] + b0, acc[mf][j][1] + b1);
            *(float2*)&out[obase[mf][1] + col] =
                make_float2(acc[mf][j][2] + b0, acc[mf][j][3] + b1);
        }
    }
}

// ------------------------------- launch ------------------------------------
extern "C" void kernel_launch(void* const* d_in, const int* in_sizes, int n_in,
                              void* d_out, int out_size)
{
    const float* x    = (const float*)d_in[0];
    const float* Wqkv = (const float*)d_in[1];
    const float* bqkv = (const float*)d_in[2];
    const float* relp = (const float*)d_in[3];
    const float* Wout = (const float*)d_in[4];
    const float* bout = (const float*)d_in[5];
    float* out = (float*)d_out;

    prep_kernel<<<576, 256>>>(Wqkv, Wout);
    convx_kernel<<<4096, 256>>>(x);
    qkv_mma<<<dim3(512, 9), 256>>>(bqkv);
    attn_kernel<<<dim3(1024, 6), 128>>>(relp);
    proj_mma<<<dim3(512, 3), 256>>>(bout, out);
}

// round 12
// speedup vs baseline: 1.3334x; 1.1486x over previous
#include <cuda_runtime.h>
#include <cuda_bf16.h>
#include <cstdint>

// ---------------------------------------------------------------------------
// WMSA round 12: traffic-fused GEMMs.
//   qkv_fused : gather+split x into resident smem A, loop all 9 N-tiles
//               (convx eliminated, A re-reads eliminated)
//   attn      : unchanged (round 11, verified)
//   proj_fused: resident A, loop 3 N-tiles, scatter epilogue
// ---------------------------------------------------------------------------

#define NWINS 1024
#define TPW   64

__device__ __align__(16) __nv_bfloat16 g_qkv_hi[(size_t)NWINS * TPW * 576];
__device__ __align__(16) __nv_bfloat16 g_qkv_lo[(size_t)NWINS * TPW * 576];
__device__ __align__(16) __nv_bfloat16 g_at_hi[(size_t)NWINS * TPW * 192];
__device__ __align__(16) __nv_bfloat16 g_at_lo[(size_t)NWINS * TPW * 192];

__device__ __align__(16) __nv_bfloat16 WqkvT_hi[576 * 192];
__device__ __align__(16) __nv_bfloat16 WqkvT_lo[576 * 192];
__device__ __align__(16) __nv_bfloat16 WoutT_hi[192 * 192];
__device__ __align__(16) __nv_bfloat16 WoutT_lo[192 * 192];

// ------------------------------ helpers ------------------------------------
__device__ __forceinline__ uint32_t smem_u32(const void* p) {
    uint32_t a;
    asm("{ .reg .u64 t; cvta.to.shared.u64 t, %1; cvt.u32.u64 %0, t; }" : "=r"(a) : "l"(p));
    return a;
}
__device__ __forceinline__ uint32_t pack2(float a, float b) {
    uint32_t r;
    asm("cvt.rn.bf16x2.f32 %0, %1, %2;" : "=r"(r) : "f"(b), "f"(a));
    return r;
}
__device__ __forceinline__ void split2(float a, float b, uint32_t& h, uint32_t& l) {
    h = pack2(a, b);
    float ha = __uint_as_float(h << 16);
    float hb = __uint_as_float(h & 0xffff0000u);
    l = pack2(a - ha, b - hb);
}
__device__ __forceinline__ void split8(const float4 v0, const float4 v1,
                                       uint4& h, uint4& l) {
    uint32_t h0, l0, h1, l1, h2, l2, h3, l3;
    split2(v0.x, v0.y, h0, l0);
    split2(v0.z, v0.w, h1, l1);
    split2(v1.x, v1.y, h2, l2);
    split2(v1.z, v1.w, h3, l3);
    h = make_uint4(h0, h1, h2, h3);
    l = make_uint4(l0, l1, l2, l3);
}
__device__ __forceinline__ void ldsm_x4(uint32_t* r, uint32_t addr) {
    asm volatile("ldmatrix.sync.aligned.m8n8.x4.shared.b16 {%0,%1,%2,%3}, [%4];"
        : "=r"(r[0]), "=r"(r[1]), "=r"(r[2]), "=r"(r[3]) : "r"(addr));
}
__device__ __forceinline__ void mma_bf16(float* c, const uint32_t* a, const uint32_t* b) {
    asm volatile("mma.sync.aligned.m16n8k16.row.col.f32.bf16.bf16.f32 "
        "{%0,%1,%2,%3}, {%4,%5,%6,%7}, {%8,%9}, {%0,%1,%2,%3};"
        : "+f"(c[0]), "+f"(c[1]), "+f"(c[2]), "+f"(c[3])
        : "r"(a[0]), "r"(a[1]), "r"(a[2]), "r"(a[3]), "r"(b[0]), "r"(b[1]));
}

// dynamic smem layout (bytes): AH[128][200], AL, BH[64][40], BL
#define SMO_AH 0
#define SMO_AL 51200
#define SMO_BH 102400
#define SMO_BL 107520
#define SM_SZ  112640

// ------------------------------ prep: weights ------------------------------
__global__ void prep_kernel(const float* __restrict__ Wqkv,
                            const float* __restrict__ Wout)
{
    int i = blockIdx.x * 256 + threadIdx.x;
    if (i < 576 * 192) {
        int n = i / 192, k = i % 192;
        float v = Wqkv[(size_t)k * 576 + n];
        __nv_bfloat16 h = __float2bfloat16(v);
        WqkvT_hi[i] = h;
        WqkvT_lo[i] = __float2bfloat16(v - __bfloat162float(h));
    }
    int j = i - 576 * 192;
    if (j >= 0 && j < 192 * 192) {
        int n = j / 192, k = j % 192;
        float v = Wout[(size_t)k * 192 + n];
        __nv_bfloat16 h = __float2bfloat16(v);
        WoutT_hi[j] = h;
        WoutT_lo[j] = __float2bfloat16(v - __bfloat162float(h));
    }
}

// ---------------------- fused GEMM compute (shared) ------------------------
// A resident [128][200] hi/lo in smem; B staged per 32-K chunk [64][40].
// One N-tile (64 cols): 6 K-chunks, warp tile 32x32 (8 warps: 4m x 2n).
template <typename EpiFn>
__device__ __forceinline__ void fused_ntile(
    uint8_t* smem, const __nv_bfloat16* __restrict__ gBh,
    const __nv_bfloat16* __restrict__ gBl, EpiFn epi)
{
    const int tid = threadIdx.x, lane = tid & 31, wid = tid >> 5;
    const int m0 = (wid & 3) * 32, n0 = (wid >> 2) * 32;
    const int brow = tid >> 2, bq = tid & 3;

    const uint32_t sAH = smem_u32(smem + SMO_AH), sAL = smem_u32(smem + SMO_AL);
    const uint32_t sBH = smem_u32(smem + SMO_BH), sBL = smem_u32(smem + SMO_BL);
    __nv_bfloat16* BH = (__nv_bfloat16*)(smem + SMO_BH);
    __nv_bfloat16* BL = (__nv_bfloat16*)(smem + SMO_BL);

    const uint4* gB_h = (const uint4*)(gBh + (size_t)brow * 192 + bq * 8);
    const uint4* gB_l = (const uint4*)(gBl + (size_t)brow * 192 + bq * 8);

    float acc[2][4][4] = {};
    uint4 bPh = gB_h[0], bPl = gB_l[0];

    for (int kc = 0; kc < 6; ++kc) {
        __syncthreads();
        *(uint4*)&BH[brow * 40 + bq * 8] = bPh;
        *(uint4*)&BL[brow * 40 + bq * 8] = bPl;
        __syncthreads();
        if (kc < 5) {
            bPh = gB_h[(kc + 1) * 4];
            bPl = gB_l[(kc + 1) * 4];
        }
        #pragma unroll
        for (int ks = 0; ks < 2; ++ks) {
            uint32_t aH[2][4], aL[2][4], bH[8], bL[8];
            #pragma unroll
            for (int mf = 0; mf < 2; ++mf) {
                uint32_t off = (uint32_t)((m0 + mf * 16 + (lane & 15)) * 400
                                          + (kc * 4 + ks * 2 + (lane >> 4)) * 16);
                ldsm_x4(aH[mf], sAH + off);
                ldsm_x4(aL[mf], sAL + off);
            }
            #pragma unroll
            for (int nf = 0; nf < 2; ++nf) {
                uint32_t off = (uint32_t)((n0 + nf * 16 + ((lane >> 4) & 1) * 8 + (lane & 7)) * 80
                                          + (ks * 2 + ((lane >> 3) & 1)) * 16);
                ldsm_x4(&bH[nf * 4], sBH + off);
                ldsm_x4(&bL[nf * 4], sBL + off);
            }
            // pass-major (independent accumulator chains)
            #pragma unroll
            for (int mf = 0; mf < 2; ++mf)
                #pragma unroll
                for (int j = 0; j < 4; ++j)
                    mma_bf16(acc[mf][j], aH[mf], &bH[j * 2]);
            #pragma unroll
            for (int mf = 0; mf < 2; ++mf)
                #pragma unroll
                for (int j = 0; j < 4; ++j)
                    mma_bf16(acc[mf][j], aH[mf], &bL[j * 2]);
            #pragma unroll
            for (int mf = 0; mf < 2; ++mf)
                #pragma unroll
                for (int j = 0; j < 4; ++j)
                    mma_bf16(acc[mf][j], aL[mf], &bH[j * 2]);
        }
    }
    epi(acc);
}

// ------------------------------ K1: QKV fused ------------------------------
// grid 512, block 256, dyn smem. Gathers x (roll -2 + window map), splits to
// resident A, loops 9 N-tiles, emits bf16 hi/lo qkv planes.
__global__ __launch_bounds__(256) void qkv_fused(
    const float* __restrict__ x, const float* __restrict__ bqkv)
{
    extern __shared__ __align__(16) uint8_t smem[];
    const int tid = threadIdx.x, lane = tid & 31, wid = tid >> 5;
    const int mt = blockIdx.x;
    const int m0 = (wid & 3) * 32, n0 = (wid >> 2) * 32;

    {   // gather + convert: 2 threads per row, 96 floats each
        const int row = tid >> 1, half = tid & 1;
        const int rowg = mt * 128 + row;
        const int tok = rowg & 63, bw = rowg >> 6;
        const int b = bw >> 9, w = bw & 511;
        const int z  = (((w >> 6) << 2)       + (tok >> 4)       + 2) & 31;
        const int y  = ((((w >> 3) & 7) << 2) + ((tok >> 2) & 3) + 2) & 31;
        const int xx = (((w & 7) << 2)        + (tok & 3)        + 2) & 31;
        const float4* xr4 = (const float4*)(
            x + ((((size_t)b * 32 + z) * 32 + y) * 32 + xx) * 192 + half * 96);
        __nv_bfloat16* aH = (__nv_bfloat16*)(smem + SMO_AH) + row * 200 + half * 96;
        __nv_bfloat16* aL = (__nv_bfloat16*)(smem + SMO_AL) + row * 200 + half * 96;
        #pragma unroll
        for (int i = 0; i < 12; ++i) {
            uint4 h, l;
            split8(xr4[2 * i], xr4[2 * i + 1], h, l);
            *(uint4*)&aH[i * 8] = h;
            *(uint4*)&aL[i * 8] = l;
        }
    }

    const int rbase = mt * 128 + m0 + (lane >> 2);
    for (int nt = 0; nt < 9; ++nt) {
        fused_ntile(smem,
            WqkvT_hi + (size_t)nt * 64 * 192, WqkvT_lo + (size_t)nt * 64 * 192,
            [&](float acc[2][4][4]) {
                #pragma unroll
                for (int j = 0; j < 4; ++j) {
                    int col = nt * 64 + n0 + j * 8 + (lane & 3) * 2;
                    float b0 = __ldg(&bqkv[col]), b1 = __ldg(&bqkv[col + 1]);
                    #pragma unroll
                    for (int mf = 0; mf < 2; ++mf) {
                        uint32_t h0, l0, h1, l1;
                        split2(acc[mf][j][0] + b0, acc[mf][j][1] + b1, h0, l0);
                        split2(acc[mf][j][2] + b0, acc[mf][j][3] + b1, h1, l1);
                        size_t i0 = (size_t)(rbase + mf * 16) * 576 + col;
                        size_t i1 = (size_t)(rbase + mf * 16 + 8) * 576 + col;
                        *(uint32_t*)&g_qkv_hi[i0] = h0;
                        *(uint32_t*)&g_qkv_lo[i0] = l0;
                        *(uint32_t*)&g_qkv_hi[i1] = h1;
                        *(uint32_t*)&g_qkv_lo[i1] = l1;
                    }
                }
            });
    }
}

// ------------------------------ K2: attention (round 11) -------------------
__global__ __launch_bounds__(128) void attn_kernel(const float* __restrict__ relp)
{
    __shared__ __nv_bfloat16 qHs[64 * 40], qLs[64 * 40];
    __shared__ __nv_bfloat16 kHs[64 * 40], kLs[64 * 40];
    __shared__ __nv_bfloat16 vHs[32 * 72], vLs[32 * 72];
    __shared__ float relS[343];

    const int bw = blockIdx.x, h = blockIdx.y;
    const int w = bw & 511;
    const int wz = w >> 6, wy = (w >> 3) & 7, wx = w & 7;
    const int tid = threadIdx.x, lane = tid & 31, wrp = tid >> 5;
    const int mb = wrp * 16;
    const float scale = 0.17677669529663687f;

    for (int i = tid; i < 343; i += 128) relS[i] = relp[h * 343 + i];

    {
        const int srow = tid & 63, sel = tid >> 6;
        size_t base = ((size_t)bw * 64 + srow) * 576 + h * 32 + (size_t)sel * 192;
        __nv_bfloat16* dH = sel ? kHs : qHs;
        __nv_bfloat16* dL = sel ? kLs : qLs;
        #pragma unroll
        for (int u = 0; u < 4; ++u) {
            *(uint4*)&dH[srow * 40 + u * 8] = *(const uint4*)&g_qkv_hi[base + u * 8];
            *(uint4*)&dL[srow * 40 + u * 8] = *(const uint4*)&g_qkv_lo[base + u * 8];
        }
        if (tid < 64) {
            size_t vb = ((size_t)bw * 64 + tid) * 576 + h * 32 + 384;
            uint4 vh[4], vl[4];
            #pragma unroll
            for (int u = 0; u < 4; ++u) {
                vh[u] = *(const uint4*)&g_qkv_hi[vb + u * 8];
                vl[u] = *(const uint4*)&g_qkv_lo[vb + u * 8];
            }
            const __nv_bfloat16* ph = (const __nv_bfloat16*)vh;
            const __nv_bfloat16* pl = (const __nv_bfloat16*)vl;
            #pragma unroll
            for (int c = 0; c < 32; ++c) {
                vHs[c * 72 + tid] = ph[c];
                vLs[c * 72 + tid] = pl[c];
            }
        }
    }
    __syncthreads();

    const uint32_t sQH = smem_u32(qHs), sQL = smem_u32(qLs);
    const uint32_t sKH = smem_u32(kHs), sKL = smem_u32(kLs);
    const uint32_t sVH = smem_u32(vHs), sVL = smem_u32(vLs);

    float s[8][4];
    #pragma unroll
    for (int b2 = 0; b2 < 8; ++b2)
        #pragma unroll
        for (int c = 0; c < 4; ++c) s[b2][c] = 0.0f;

    #pragma unroll
    for (int ks = 0; ks < 2; ++ks) {
        uint32_t aH[4], aL[4], bH[4][4], bL[4][4];
        {
            uint32_t off = (uint32_t)((mb + (lane & 15)) * 80
                                      + (ks * 2 + (lane >> 4)) * 16);
            ldsm_x4(aH, sQH + off);
            ldsm_x4(aL, sQL + off);
        }
        #pragma unroll
        for (int grp = 0; grp < 4; ++grp) {
            uint32_t off = (uint32_t)((grp * 16 + ((lane >> 4) & 1) * 8 + (lane & 7)) * 80
                                      + (ks * 2 + ((lane >> 3) & 1)) * 16);
            ldsm_x4(bH[grp], sKH + off);
            ldsm_x4(bL[grp], sKL + off);
        }
        #pragma unroll
        for (int grp = 0; grp < 4; ++grp)
            #pragma unroll
            for (int j = 0; j < 2; ++j)
                mma_bf16(s[grp * 2 + j], aH, &bH[grp][j * 2]);
        #pragma unroll
        for (int grp = 0; grp < 4; ++grp)
            #pragma unroll
            for (int j = 0; j < 2; ++j)
                mma_bf16(s[grp * 2 + j], aH, &bL[grp][j * 2]);
        #pragma unroll
        for (int grp = 0; grp < 4; ++grp)
            #pragma unroll
            for (int j = 0; j < 2; ++j)
                mma_bf16(s[grp * 2 + j], aL, &bH[grp][j * 2]);
    }

    const int g = lane >> 2, tg2 = (lane & 3) * 2;
    int linP[2]; bool pz2[2], py2[2], px2[2];
    #pragma unroll
    for (int r = 0; r < 2; ++r) {
        int p = mb + g + r * 8;
        int pz = p >> 4, py = (p >> 2) & 3, px = p & 3;
        linP[r] = pz * 49 + py * 7 + px;
        pz2[r] = pz < 2; py2[r] = py < 2; px2[r] = px < 2;
    }
    int linQ[16]; bool qz2[16], qy2[16], qx2[16];
    #pragma unroll
    for (int nt = 0; nt < 8; ++nt)
        #pragma unroll
        for (int t = 0; t < 2; ++t) {
            int qq = nt * 8 + tg2 + t;
            int qz = qq >> 4, qy = (qq >> 2) & 3, qx = qq & 3;
            linQ[nt * 2 + t] = qz * 49 + qy * 7 + qx;
            qz2[nt * 2 + t] = qz < 2; qy2[nt * 2 + t] = qy < 2; qx2[nt * 2 + t] = qx < 2;
        }
    const bool mz = (wz == 7), my = (wy == 7), mx = (wx == 7);
    #pragma unroll
    for (int nt = 0; nt < 8; ++nt)
        #pragma unroll
        for (int r = 0; r < 2; ++r)
            #pragma unroll
            for (int t = 0; t < 2; ++t) {
                int qi = nt * 2 + t;
                float v = s[nt][r * 2 + t] * scale
                        + relS[linP[r] - linQ[qi] + 171];
                if ((mz && (pz2[r] != qz2[qi])) ||
                    (my && (py2[r] != qy2[qi])) ||
                    (mx && (px2[r] != qx2[qi]))) v = -1e30f;
                s[nt][r * 2 + t] = v;
            }

    float inv[2];
    #pragma unroll
    for (int r = 0; r < 2; ++r) {
        float mxv = -1e30f;
        #pragma unroll
        for (int nt = 0; nt < 8; ++nt)
            #pragma unroll
            for (int t = 0; t < 2; ++t)
                mxv = fmaxf(mxv, s[nt][r * 2 + t]);
        mxv = fmaxf(mxv, __shfl_xor_sync(0xffffffffu, mxv, 1));
        mxv = fmaxf(mxv, __shfl_xor_sync(0xffffffffu, mxv, 2));
        float sum = 0.0f;
        #pragma unroll
        for (int nt = 0; nt < 8; ++nt)
            #pragma unroll
            for (int t = 0; t < 2; ++t) {
                float e = __expf(s[nt][r * 2 + t] - mxv);
                s[nt][r * 2 + t] = e;
                sum += e;
            }
        sum += __shfl_xor_sync(0xffffffffu, sum, 1);
        sum += __shfl_xor_sync(0xffffffffu, sum, 2);
        inv[r] = 1.0f / sum;
    }

    float o[4][4];
    #pragma unroll
    for (int b2 = 0; b2 < 4; ++b2)
        #pragma unroll
        for (int c = 0; c < 4; ++c) o[b2][c] = 0.0f;

    #pragma unroll
    for (int ks = 0; ks < 4; ++ks) {
        uint32_t bH[2][4], bL[2][4];
        #pragma unroll
        for (int grp = 0; grp < 2; ++grp) {
            uint32_t off = (uint32_t)((grp * 16 + ((lane >> 4) & 1) * 8 + (lane & 7)) * 144
                                      + (ks * 2 + ((lane >> 3) & 1)) * 16);
            ldsm_x4(bH[grp], sVH + off);
            ldsm_x4(bL[grp], sVL + off);
        }
        uint32_t aPH[4], aPL[4];
        split2(s[2 * ks][0],     s[2 * ks][1],     aPH[0], aPL[0]);
        split2(s[2 * ks][2],     s[2 * ks][3],     aPH[1], aPL[1]);
        split2(s[2 * ks + 1][0], s[2 * ks + 1][1], aPH[2], aPL[2]);
        split2(s[2 * ks + 1][2], s[2 * ks + 1][3], aPH[3], aPL[3]);
        #pragma unroll
        for (int grp = 0; grp < 2; ++grp)
            #pragma unroll
            for (int j = 0; j < 2; ++j)
                mma_bf16(o[grp * 2 + j], aPH, &bH[grp][j * 2]);
        #pragma unroll
        for (int grp = 0; grp < 2; ++grp)
            #pragma unroll
            for (int j = 0; j < 2; ++j)
                mma_bf16(o[grp * 2 + j], aPH, &bL[grp][j * 2]);
        #pragma unroll
        for (int grp = 0; grp < 2; ++grp)
            #pragma unroll
            for (int j = 0; j < 2; ++j)
                mma_bf16(o[grp * 2 + j], aPL, &bH[grp][j * 2]);
    }

    {
        int r0 = mb + g;
        #pragma unroll
        for (int nt = 0; nt < 4; ++nt) {
            int col = h * 32 + nt * 8 + tg2;
            uint32_t h0, l0, h1, l1;
            split2(o[nt][0] * inv[0], o[nt][1] * inv[0], h0, l0);
            split2(o[nt][2] * inv[1], o[nt][3] * inv[1], h1, l1);
            size_t i0 = ((size_t)bw * 64 + r0) * 192 + col;
            size_t i1 = ((size_t)bw * 64 + r0 + 8) * 192 + col;
            *(uint32_t*)&g_at_hi[i0] = h0;
            *(uint32_t*)&g_at_lo[i0] = l0;
            *(uint32_t*)&g_at_hi[i1] = h1;
            *(uint32_t*)&g_at_lo[i1] = l1;
        }
    }
}

// ------------------------------ K3: out proj fused -------------------------
// grid 512, block 256, dyn smem. Copies resident A (bf16 planes), loops 3
// N-tiles, scatter epilogue (inverse window + roll +2).
__global__ __launch_bounds__(256) void proj_fused(
    const float* __restrict__ bout, float* __restrict__ out)
{
    extern __shared__ __align__(16) uint8_t smem[];
    const int tid = threadIdx.x, lane = tid & 31, wid = tid >> 5;
    const int mt = blockIdx.x;
    const int m0 = (wid & 3) * 32, n0 = (wid >> 2) * 32;

    {   // copy A planes: 2 threads per row
        const int row = tid >> 1, half = tid & 1;
        const __nv_bfloat16* sH = g_at_hi + (size_t)(mt * 128 + row) * 192 + half * 96;
        const __nv_bfloat16* sL = g_at_lo + (size_t)(mt * 128 + row) * 192 + half * 96;
        __nv_bfloat16* aH = (__nv_bfloat16*)(smem + SMO_AH) + row * 200 + half * 96;
        __nv_bfloat16* aL = (__nv_bfloat16*)(smem + SMO_AL) + row * 200 + half * 96;
        #pragma unroll
        for (int i = 0; i < 12; ++i) {
            *(uint4*)&aH[i * 8] = *(const uint4*)&sH[i * 8];
            *(uint4*)&aL[i * 8] = *(const uint4*)&sL[i * 8];
        }
    }

    // scatter bases (col-independent)
    size_t obase[2][2];
    #pragma unroll
    for (int mf = 0; mf < 2; ++mf)
        #pragma unroll
        for (int rr = 0; rr < 2; ++rr) {
            int rg = mt * 128 + m0 + mf * 16 + rr * 8 + (lane >> 2);
            int tok = rg & 63, bw = rg >> 6;
            int b = bw >> 9, w = bw & 511;
            int z  = (((w >> 6) << 2)       + (tok >> 4)       + 2) & 31;
            int y  = ((((w >> 3) & 7) << 2) + ((tok >> 2) & 3) + 2) & 31;
            int xx = (((w & 7) << 2)        + (tok & 3)        + 2) & 31;
            obase[mf][rr] = ((((size_t)b * 32 + z) * 32 + y) * 32 + xx) * 192;
        }

    for (int nt = 0; nt < 3; ++nt) {
        fused_ntile(smem,
            WoutT_hi + (size_t)nt * 64 * 192, WoutT_lo + (size_t)nt * 64 * 192,
            [&](float acc[2][4][4]) {
                #pragma unroll
                for (int j = 0; j < 4; ++j) {
                    int col = nt * 64 + n0 + j * 8 + (lane & 3) * 2;
                    float b0 = __ldg(&bout[col]), b1 = __ldg(&bout[col + 1]);
                    #pragma unroll
                    for (int mf = 0; mf < 2; ++mf) {
                        *(float2*)&out[obase[mf][0] + col] =
                            make_float2(acc[mf][j][0] + b0, acc[mf][j][1] + b1);
                        *(float2*)&out[obase[mf][1] + col] =
                            make_float2(acc[mf][j][2] + b0, acc[mf][j][3] + b1);
                    }
                }
            });
    }
}

// ------------------------------- launch ------------------------------------
extern "C" void kernel_launch(void* const* d_in, const int* in_sizes, int n_in,
                              void* d_out, int out_size)
{
    const float* x    = (const float*)d_in[0];
    const float* Wqkv = (const float*)d_in[1];
    const float* bqkv = (const float*)d_in[2];
    const float* relp = (const float*)d_in[3];
    const float* Wout = (const float*)d_in[4];
    const float* bout = (const float*)d_in[5];
    float* out = (float*)d_out;

    cudaFuncSetAttribute(qkv_fused,  cudaFuncAttributeMaxDynamicSharedMemorySize, SM_SZ);
    cudaFuncSetAttribute(proj_fused, cudaFuncAttributeMaxDynamicSharedMemorySize, SM_SZ);

    prep_kernel<<<576, 256>>>(Wqkv, Wout);
    qkv_fused<<<512, 256, SM_SZ>>>(x, bqkv);
    attn_kernel<<<dim3(1024, 6), 128>>>(relp);
    proj_fused<<<512, 256, SM_SZ>>>(bout, out);
}